// round 3
// baseline (speedup 1.0000x reference)
#include <cuda_runtime.h>

#define NBATCH 16
#define NPT    4096
#define NQ     1024
#define NSAMP  32
#define OUT1SZ (NBATCH*3*NQ)        // 49152
#define OUT2SZ (NBATCH*128*NQ)      // 2097152
#define MAXE   (NBATCH*NQ*NSAMP + 64)
#define FULLM  0xffffffffu

__device__ int      g_fps[NBATCH*NQ];
__device__ unsigned g_ent[MAXE];
__device__ int      g_ecnt;
__device__ float    g_W0[67*64];    // [c][o] folded BN
__device__ float    g_B0[64];
__device__ float    g_W1[64*64];    // [c][o]
__device__ float    g_B1[64];
__device__ float    g_W2[64*128];   // [k][o]
__device__ float    g_B2[128];

// ---------------- prep: zero out2, fold BN into weights, reset counter ----
__global__ void prep_kernel(float* __restrict__ out2,
    const float* w0,const float* b0,const float* g0,const float* be0,const float* m0,const float* v0,
    const float* w1,const float* b1,const float* g1,const float* be1,const float* m1,const float* v1,
    const float* w2,const float* b2,const float* g2,const float* be2,const float* m2,const float* v2)
{
    int idx = blockIdx.x*blockDim.x + threadIdx.x;
    if (idx < OUT2SZ/4) ((float4*)out2)[idx] = make_float4(0.f,0.f,0.f,0.f);
    if (blockIdx.x == 0) {
        int t = threadIdx.x;
        if (t == 0) g_ecnt = 0;
        for (int i=t;i<67*64;i+=blockDim.x){int c=i>>6,o=i&63;float s=g0[o]*rsqrtf(v0[o]+1e-5f);g_W0[i]=w0[o*67+c]*s;}
        for (int i=t;i<64*64;i+=blockDim.x){int c=i>>6,o=i&63;float s=g1[o]*rsqrtf(v1[o]+1e-5f);g_W1[i]=w1[o*64+c]*s;}
        for (int i=t;i<64*128;i+=blockDim.x){int k=i>>7,o=i&127;float s=g2[o]*rsqrtf(v2[o]+1e-5f);g_W2[i]=w2[o*64+k]*s;}
        if (t<64){float s=g0[t]*rsqrtf(v0[t]+1e-5f);g_B0[t]=(b0[t]-m0[t])*s+be0[t];}
        if (t<64){float s=g1[t]*rsqrtf(v1[t]+1e-5f);g_B1[t]=(b1[t]-m1[t])*s+be1[t];}
        if (t<128){float s=g2[t]*rsqrtf(v2[t]+1e-5f);g_B2[t]=(b2[t]-m2[t])*s+be2[t];}
    }
}

// ---------------- FPS: one CTA/batch, ONE barrier per iteration ----------
// Coordinates of the winner travel with the reduction (shfl + per-warp smem
// slot, double-buffered on parity) so no second barrier is needed.
// Fused: writes new_xyz (out1) at the end.
__global__ void __launch_bounds__(1024,1) fps_kernel(const float* __restrict__ xyz,
                                                     float* __restrict__ out1)
{
    __shared__ unsigned s_v[2][32], s_ix[2][32];
    __shared__ float    s_x[2][32], s_y[2][32], s_z[2][32];
    __shared__ float    s_init[3];
    int b = blockIdx.x, t = threadIdx.x;
    const float* X = xyz + b*3*NPT;
    int base = t*4;
    float4 vx = *(const float4*)(X + base);
    float4 vy = *(const float4*)(X + NPT + base);
    float4 vz = *(const float4*)(X + 2*NPT + base);
    float px[4]={vx.x,vx.y,vx.z,vx.w};
    float py[4]={vy.x,vy.y,vy.z,vy.w};
    float pz[4]={vz.x,vz.y,vz.z,vz.w};
    float dd[4]={1e10f,1e10f,1e10f,1e10f};
    int lane = t & 31, wid = t >> 5;
    if (t == 0){ s_init[0]=px[0]; s_init[1]=py[0]; s_init[2]=pz[0]; }
    __syncthreads();
    float cx = s_init[0], cy = s_init[1], cz = s_init[2];
    int f = 0;
    for (int it=0; it<NQ; ++it) {
        if (t == 0) g_fps[b*NQ+it] = f;
        #pragma unroll
        for (int j=0;j<4;j++){
            float dx=px[j]-cx, dy=py[j]-cy, dz=pz[j]-cz;
            // match XLA: separately-rounded squares, left-assoc sum
            float d = __fadd_rn(__fadd_rn(__fmul_rn(dx,dx),__fmul_rn(dy,dy)),__fmul_rn(dz,dz));
            dd[j] = fminf(dd[j], d);
        }
        float best = dd[0]; int bidx = base;
        #pragma unroll
        for (int j=1;j<4;j++) if (dd[j] > best){ best=dd[j]; bidx=base+j; }
        unsigned db   = __float_as_uint(best);        // >=0: uint order == float order
        unsigned wmax = __reduce_max_sync(FULLM, db);
        unsigned cand = (db==wmax) ? (unsigned)bidx : FULLM;
        unsigned widx = __reduce_min_sync(FULLM, cand);   // first-index tie-break
        // coords of winner: uniform slot jj, shfl from owner lane
        int jj = widx & 3, ol = (widx>>2) & 31;
        float mx = jj==0?px[0]:jj==1?px[1]:jj==2?px[2]:px[3];
        float my = jj==0?py[0]:jj==1?py[1]:jj==2?py[2]:py[3];
        float mz = jj==0?pz[0]:jj==1?pz[1]:jj==2?pz[2]:pz[3];
        float ox = __shfl_sync(FULLM, mx, ol);
        float oy = __shfl_sync(FULLM, my, ol);
        float oz = __shfl_sync(FULLM, mz, ol);
        int par = it & 1;
        if (lane==0){
            s_v[par][wid]=wmax; s_ix[par][wid]=widx;
            s_x[par][wid]=ox;   s_y[par][wid]=oy;   s_z[par][wid]=oz;
        }
        __syncthreads();
        unsigned vm = s_v[par][lane];
        unsigned vi = s_ix[par][lane];
        float xx = s_x[par][lane], yy = s_y[par][lane], zz = s_z[par][lane];
        unsigned bmax = __reduce_max_sync(FULLM, vm);
        unsigned cw   = (vm==bmax) ? vi : FULLM;
        unsigned fn   = __reduce_min_sync(FULLM, cw);
        unsigned wl   = __reduce_min_sync(FULLM, (cw==fn) ? (unsigned)lane : 63u);
        f  = (int)fn;
        cx = __shfl_sync(FULLM, xx, wl);
        cy = __shfl_sync(FULLM, yy, wl);
        cz = __shfl_sync(FULLM, zz, wl);
    }
    __syncthreads();   // t0's g_fps writes visible CTA-wide
    for (int i=t;i<3*NQ;i+=1024){
        int c=i>>10, s=i&1023;
        out1[b*3072 + i] = X[c*NPT + g_fps[b*NQ+s]];
    }
}

// ---------------- ball query: chunk-outer, float4, 4 queries/warp ---------
__global__ void __launch_bounds__(256) bq_kernel(const float* __restrict__ xyz,
                                                 const float* __restrict__ out1)
{
    __shared__ unsigned ebuf[8*128];     // 4KB: 4 queries * 32 max per warp
    int b = blockIdx.x >> 5, qb = blockIdx.x & 31;
    const float* Xx = xyz + b*3*NPT;
    const float* Xy = Xx + NPT;
    const float* Xz = Xx + 2*NPT;
    int wid = threadIdx.x>>5, lane = threadIdx.x&31;
    unsigned lt = (1u<<lane)-1u;
    unsigned* wbuf = ebuf + wid*128;
    int s0 = qb*32 + wid*4;
    float cx[4],cy[4],cz[4]; int cnt[4]={0,0,0,0}; unsigned gtag[4];
    #pragma unroll
    for (int q=0;q<4;q++){
        int s = s0+q;
        cx[q]=__ldg(out1 + b*3072 + s);
        cy[q]=__ldg(out1 + b*3072 + 1024 + s);
        cz[q]=__ldg(out1 + b*3072 + 2048 + s);
        gtag[q]=(unsigned)(b*NQ+s)<<12;
    }
    int wn = 0;
    for (int bp=0; bp<NPT; bp+=128){
        if (cnt[0]>=NSAMP && cnt[1]>=NSAMP && cnt[2]>=NSAMP && cnt[3]>=NSAMP) break;
        int p = bp + lane*4;
        float4 fx = __ldg((const float4*)(Xx+p));
        float4 fy = __ldg((const float4*)(Xy+p));
        float4 fz = __ldg((const float4*)(Xz+p));
        float pxl[4]={fx.x,fx.y,fx.z,fx.w};
        float pyl[4]={fy.x,fy.y,fy.z,fy.w};
        float pzl[4]={fz.x,fz.y,fz.z,fz.w};
        #pragma unroll
        for (int q=0;q<4;q++){
            if (cnt[q]>=NSAMP) continue;          // warp-uniform
            bool inb[4]; unsigned m[4];
            #pragma unroll
            for (int j=0;j<4;j++){
                float dx=pxl[j]-cx[q], dy=pyl[j]-cy[q], dz=pzl[j]-cz[q];
                float d2=__fadd_rn(__fadd_rn(__fmul_rn(dx,dx),__fmul_rn(dy,dy)),__fmul_rn(dz,dz));
                inb[j] = (d2 <= 0.04f);
                m[j] = __ballot_sync(FULLM, inb[j]);
            }
            int tot = __popc(m[0])+__popc(m[1])+__popc(m[2])+__popc(m[3]);
            if (!tot) continue;                    // warp-uniform
            if (cnt[q] + tot <= NSAMP){
                // fast path: take all (entry order irrelevant downstream)
                int off = wn;
                #pragma unroll
                for (int j=0;j<4;j++){
                    if (inb[j]) wbuf[off + __popc(m[j]&lt)] = gtag[q] | (unsigned)(p+j);
                    off += __popc(m[j]);
                }
                wn += tot; cnt[q] += tot;
            } else {
                // rare: crossing NSAMP — redo this 128-chunk in index order
                for (int sub=0; sub<4 && cnt[q]<NSAMP; ++sub){
                    int pp = bp + sub*32 + lane;
                    float dx=__ldg(Xx+pp)-cx[q], dy=__ldg(Xy+pp)-cy[q], dz=__ldg(Xz+pp)-cz[q];
                    float d2=__fadd_rn(__fadd_rn(__fmul_rn(dx,dx),__fmul_rn(dy,dy)),__fmul_rn(dz,dz));
                    bool in = (d2 <= 0.04f);
                    unsigned mask = __ballot_sync(FULLM, in);
                    int pc = __popc(mask);
                    int take = min(pc, NSAMP-cnt[q]);
                    if (in){
                        int pos = __popc(mask & lt);
                        if (pos < take) wbuf[wn+pos] = gtag[q] | (unsigned)pp;
                    }
                    wn += take; cnt[q] += take;
                }
            }
        }
    }
    int gb = 0;
    if (lane==0) gb = atomicAdd(&g_ecnt, wn);
    gb = __shfl_sync(FULLM, gb, 0);
    for (int i=lane;i<wn;i+=32) g_ent[gb+i] = wbuf[i];
}

// ---------------- fused 3-layer MLP on compacted entries + max scatter ---
__global__ void __launch_bounds__(256,2) mlp_kernel(const float* __restrict__ xyz,
                                                    const float* __restrict__ pts,
                                                    const float* __restrict__ out1,
                                                    float* __restrict__ out2)
{
    extern __shared__ float sm[];
    float* sX  = sm;            // 67*64 = 4288
    float* sH  = sm + 4288;     // 64*64 = 4096
    float* sB0 = sm + 8384;     // 64
    float* sB1 = sm + 8448;     // 64
    float* sB2 = sm + 8512;     // 128  (total 8640 floats = 34560 B)
    int t = threadIdx.x;
    if (t<64){ sB0[t]=g_B0[t]; sB1[t]=g_B1[t]; }
    if (t<128) sB2[t]=g_B2[t];
    int E = g_ecnt;
    int tiles = (E+63)>>6;
    int tx = t&15, ty = t>>4;
    int* outI = (int*)out2;
    int le = t>>2, sub = t&3;
    for (int tb = blockIdx.x; tb < tiles; tb += gridDim.x){
        int tbase = tb<<6;
        __syncthreads();                       // prev tile done reading sX/sH
        {   // gather 67-channel input for 64 entries (4 threads / entry)
            int ge = tbase + le;
            unsigned raw = g_ent[ge < E ? ge : 0] & 0x3FFFFFFu;
            int p = raw & 4095; int g = raw >> 12; int bb = g >> 10, s = g & 1023;
            const float* pc = pts  + (size_t)(bb*64)*NPT + p;
            const float* xc = xyz  + (size_t)(bb*3)*NPT + p;
            const float* cc = out1 + bb*3*NQ + s;
            for (int c=sub;c<67;c+=4){
                float v;
                if (c<3) v = __ldg(xc + c*NPT) - __ldg(cc + c*NQ);
                else     v = __ldg(pc + (c-3)*NPT);
                sX[c*64+le] = v;
            }
        }
        __syncthreads();
        // ---- layer 0: 67 -> 64 ----
        float acc[4][4];
        #pragma unroll
        for (int j=0;j<4;j++){ float bb=sB0[ty*4+j];
            #pragma unroll
            for (int i=0;i<4;i++) acc[i][j]=bb; }
        #pragma unroll 4
        for (int k=0;k<67;k++){
            float4 xv = *(const float4*)&sX[k*64+tx*4];
            float4 wv = __ldg((const float4*)&g_W0[k*64+ty*4]);
            float xr[4]={xv.x,xv.y,xv.z,xv.w};
            float wr[4]={wv.x,wv.y,wv.z,wv.w};
            #pragma unroll
            for (int i=0;i<4;i++)
                #pragma unroll
                for (int j=0;j<4;j++) acc[i][j] = fmaf(xr[i],wr[j],acc[i][j]);
        }
        #pragma unroll
        for (int j=0;j<4;j++){
            float4 hv = make_float4(fmaxf(acc[0][j],0.f),fmaxf(acc[1][j],0.f),
                                    fmaxf(acc[2][j],0.f),fmaxf(acc[3][j],0.f));
            *(float4*)&sH[(ty*4+j)*64 + tx*4] = hv;
        }
        __syncthreads();
        // ---- layer 1: 64 -> 64 (reads sH, writes sX) ----
        #pragma unroll
        for (int j=0;j<4;j++){ float bb=sB1[ty*4+j];
            #pragma unroll
            for (int i=0;i<4;i++) acc[i][j]=bb; }
        #pragma unroll 4
        for (int k=0;k<64;k++){
            float4 xv = *(const float4*)&sH[k*64+tx*4];
            float4 wv = __ldg((const float4*)&g_W1[k*64+ty*4]);
            float xr[4]={xv.x,xv.y,xv.z,xv.w};
            float wr[4]={wv.x,wv.y,wv.z,wv.w};
            #pragma unroll
            for (int i=0;i<4;i++)
                #pragma unroll
                for (int j=0;j<4;j++) acc[i][j] = fmaf(xr[i],wr[j],acc[i][j]);
        }
        #pragma unroll
        for (int j=0;j<4;j++){
            float4 hv = make_float4(fmaxf(acc[0][j],0.f),fmaxf(acc[1][j],0.f),
                                    fmaxf(acc[2][j],0.f),fmaxf(acc[3][j],0.f));
            *(float4*)&sX[(ty*4+j)*64 + tx*4] = hv;
        }
        __syncthreads();
        // ---- layer 2: 64 -> 128 + relu + merged atomicMax scatter ----
        float a2[4][8];
        #pragma unroll
        for (int j=0;j<8;j++){ float bb=sB2[ty*8+j];
            #pragma unroll
            for (int i=0;i<4;i++) a2[i][j]=bb; }
        #pragma unroll 2
        for (int k=0;k<64;k++){
            float4 xv = *(const float4*)&sX[k*64+tx*4];
            float4 wa = __ldg((const float4*)&g_W2[k*128+ty*8]);
            float4 wb = __ldg((const float4*)&g_W2[k*128+ty*8+4]);
            float xr[4]={xv.x,xv.y,xv.z,xv.w};
            float wr[8]={wa.x,wa.y,wa.z,wa.w,wb.x,wb.y,wb.z,wb.w};
            #pragma unroll
            for (int i=0;i<4;i++)
                #pragma unroll
                for (int j=0;j<8;j++) a2[i][j]=fmaf(xr[i],wr[j],a2[i][j]);
        }
        // consecutive entries are usually the same group: merge before atomics
        unsigned gid[4];
        #pragma unroll
        for (int i=0;i<4;i++){
            int ge = tbase + tx*4 + i;
            gid[i] = (ge < E) ? ((g_ent[ge] >> 12) & 0x3FFFu) : 0xFFFFFFFFu;
        }
        #pragma unroll
        for (int i=0;i<4;i++){
            if (gid[i]==0xFFFFFFFFu) continue;
            if (i>0 && gid[i]==gid[i-1]) continue;      // merged into earlier head
            float mv[8];
            #pragma unroll
            for (int j=0;j<8;j++) mv[j]=a2[i][j];
            #pragma unroll
            for (int i2=1;i2<4;i2++){
                if (i+i2<4 && gid[i+i2]==gid[i]){
                    #pragma unroll
                    for (int j=0;j<8;j++) mv[j]=fmaxf(mv[j],a2[i+i2][j]);
                }
            }
            int bb = gid[i]>>10, s = gid[i]&1023;
            int* po = outI + (bb*128 + ty*8)*NQ + s;
            #pragma unroll
            for (int j=0;j<8;j++)
                atomicMax(po + j*NQ, __float_as_int(fmaxf(mv[j],0.f)));
        }
    }
}

extern "C" void kernel_launch(void* const* d_in, const int* in_sizes, int n_in,
                              void* d_out, int out_size)
{
    const float* xyz = (const float*)d_in[0];
    const float* pts = (const float*)d_in[1];
    float* out1 = (float*)d_out;
    float* out2 = out1 + OUT1SZ;

    prep_kernel<<<2048,256>>>(out2,
        (const float*)d_in[2],(const float*)d_in[3],(const float*)d_in[4],
        (const float*)d_in[5],(const float*)d_in[6],(const float*)d_in[7],
        (const float*)d_in[8],(const float*)d_in[9],(const float*)d_in[10],
        (const float*)d_in[11],(const float*)d_in[12],(const float*)d_in[13],
        (const float*)d_in[14],(const float*)d_in[15],(const float*)d_in[16],
        (const float*)d_in[17],(const float*)d_in[18],(const float*)d_in[19]);
    fps_kernel<<<16,1024>>>(xyz, out1);
    bq_kernel<<<512,256>>>(xyz, out1);
    mlp_kernel<<<296,256,34560>>>(xyz, pts, out1, out2);
}

// round 4
// speedup vs baseline: 1.5403x; 1.5403x over previous
#include <cuda_runtime.h>

#define NBATCH 16
#define NPT    4096
#define NQ     1024
#define NSAMP  32
#define OUT1SZ (NBATCH*3*NQ)        // 49152
#define OUT2SZ (NBATCH*128*NQ)      // 2097152
#define MAXE   (NBATCH*NQ*NSAMP + 64)
#define FULLM  0xffffffffu

__device__ int      g_fps[NBATCH*NQ];
__device__ unsigned g_ent[MAXE];
__device__ int      g_ecnt;
__device__ float    g_W0[67*64];    // [c][o] folded BN
__device__ float    g_B0[64];
__device__ float    g_W1[64*64];    // [c][o]
__device__ float    g_B1[64];
__device__ float    g_W2[64*128];   // [k][o]
__device__ float    g_B2[128];

// ---- f32x2 packed helpers: two independent .rn fp32 ops per instruction --
__device__ __forceinline__ unsigned long long pk2(float a, float b){
    unsigned long long r; asm("mov.b64 %0,{%1,%2};":"=l"(r):"f"(a),"f"(b)); return r;
}
__device__ __forceinline__ void upk2(unsigned long long v, float&a, float&b){
    asm("mov.b64 {%0,%1},%2;":"=f"(a),"=f"(b):"l"(v));
}
__device__ __forceinline__ unsigned long long add2(unsigned long long a, unsigned long long b){
    unsigned long long r; asm("add.rn.f32x2 %0,%1,%2;":"=l"(r):"l"(a),"l"(b)); return r;
}
__device__ __forceinline__ unsigned long long mul2(unsigned long long a, unsigned long long b){
    unsigned long long r; asm("mul.rn.f32x2 %0,%1,%2;":"=l"(r):"l"(a),"l"(b)); return r;
}

// ---------------- prep: zero out2, fold BN into weights, reset counter ----
__global__ void prep_kernel(float* __restrict__ out2,
    const float* w0,const float* b0,const float* g0,const float* be0,const float* m0,const float* v0,
    const float* w1,const float* b1,const float* g1,const float* be1,const float* m1,const float* v1,
    const float* w2,const float* b2,const float* g2,const float* be2,const float* m2,const float* v2)
{
    int idx = blockIdx.x*blockDim.x + threadIdx.x;
    if (idx < OUT2SZ/4) ((float4*)out2)[idx] = make_float4(0.f,0.f,0.f,0.f);
    if (blockIdx.x == 0) {
        int t = threadIdx.x;
        if (t == 0) g_ecnt = 0;
        for (int i=t;i<67*64;i+=blockDim.x){int c=i>>6,o=i&63;float s=g0[o]*rsqrtf(v0[o]+1e-5f);g_W0[i]=w0[o*67+c]*s;}
        for (int i=t;i<64*64;i+=blockDim.x){int c=i>>6,o=i&63;float s=g1[o]*rsqrtf(v1[o]+1e-5f);g_W1[i]=w1[o*64+c]*s;}
        for (int i=t;i<64*128;i+=blockDim.x){int k=i>>7,o=i&127;float s=g2[o]*rsqrtf(v2[o]+1e-5f);g_W2[i]=w2[o*64+k]*s;}
        if (t<64){float s=g0[t]*rsqrtf(v0[t]+1e-5f);g_B0[t]=(b0[t]-m0[t])*s+be0[t];}
        if (t<64){float s=g1[t]*rsqrtf(v1[t]+1e-5f);g_B1[t]=(b1[t]-m1[t])*s+be1[t];}
        if (t<128){float s=g2[t]*rsqrtf(v2[t]+1e-5f);g_B2[t]=(b2[t]-m2[t])*s+be2[t];}
    }
}

// ---------------- FPS: 512 thr/CTA, 8 pts/thread, f32x2, 1 barrier -------
__global__ void __launch_bounds__(512,1) fps_kernel(const float* __restrict__ xyz,
                                                    float* __restrict__ out1)
{
    __shared__ unsigned s_v[2][16], s_ix[2][16];
    int b = blockIdx.x, t = threadIdx.x;
    int lane = t & 31, wid = t >> 5;
    const float* X = xyz + b*3*NPT;
    int base = t*8;
    float px[8],py[8],pz[8],dd[8];
    {
        float4 a0 = *(const float4*)(X + base);
        float4 a1 = *(const float4*)(X + base + 4);
        float4 b0 = *(const float4*)(X + NPT + base);
        float4 b1 = *(const float4*)(X + NPT + base + 4);
        float4 c0 = *(const float4*)(X + 2*NPT + base);
        float4 c1 = *(const float4*)(X + 2*NPT + base + 4);
        px[0]=a0.x;px[1]=a0.y;px[2]=a0.z;px[3]=a0.w;px[4]=a1.x;px[5]=a1.y;px[6]=a1.z;px[7]=a1.w;
        py[0]=b0.x;py[1]=b0.y;py[2]=b0.z;py[3]=b0.w;py[4]=b1.x;py[5]=b1.y;py[6]=b1.z;py[7]=b1.w;
        pz[0]=c0.x;pz[1]=c0.y;pz[2]=c0.z;pz[3]=c0.w;pz[4]=c1.x;pz[5]=c1.y;pz[6]=c1.z;pz[7]=c1.w;
    }
    unsigned long long px2[4],py2[4],pz2[4];
    #pragma unroll
    for (int p=0;p<4;p++){ px2[p]=pk2(px[2*p],px[2*p+1]); py2[p]=pk2(py[2*p],py[2*p+1]); pz2[p]=pk2(pz[2*p],pz[2*p+1]); }
    #pragma unroll
    for (int j=0;j<8;j++) dd[j]=1e10f;
    float cx=__ldg(X), cy=__ldg(X+NPT), cz=__ldg(X+2*NPT);
    int f = 0;
    for (int it=0; it<NQ; ++it) {
        if (t == 0) g_fps[b*NQ+it] = f;
        unsigned long long ncx=pk2(-cx,-cx), ncy=pk2(-cy,-cy), ncz=pk2(-cz,-cz);
        #pragma unroll
        for (int p=0;p<4;p++){
            // (px-cx)^2 + (py-cy)^2 + (pz-cz)^2, each op .rn, left-assoc sum
            unsigned long long dx=add2(px2[p],ncx), dy=add2(py2[p],ncy), dz=add2(pz2[p],ncz);
            unsigned long long d2=add2(add2(mul2(dx,dx),mul2(dy,dy)),mul2(dz,dz));
            float dlo,dhi; upk2(d2,dlo,dhi);
            dd[2*p]   = fminf(dd[2*p],   dlo);
            dd[2*p+1] = fminf(dd[2*p+1], dhi);
        }
        float best = dd[0]; int bidx = base;
        #pragma unroll
        for (int j=1;j<8;j++) if (dd[j] > best){ best=dd[j]; bidx=base+j; }
        unsigned db   = __float_as_uint(best);        // >=0: uint order == float order
        unsigned wmax = __reduce_max_sync(FULLM, db);
        unsigned mk   = __ballot_sync(FULLM, db==wmax);
        int src = __ffs(mk)-1;                         // lowest lane = lowest index
        unsigned widx = __shfl_sync(FULLM, (unsigned)bidx, src);
        int par = it & 1;
        if (lane==0){ s_v[par][wid]=wmax; s_ix[par][wid]=widx; }
        __syncthreads();
        unsigned vm   = s_v[par][lane & 15];
        unsigned bmax = __reduce_max_sync(FULLM, vm);
        unsigned mk2  = __ballot_sync(FULLM, vm==bmax);
        int src2 = __ffs(mk2)-1;                       // <16, lowest warp = lowest index
        f = (int)s_ix[par][src2];                      // uniform smem read
        cx=__ldg(X+f); cy=__ldg(X+NPT+f); cz=__ldg(X+2*NPT+f);   // broadcast L1 hit
    }
    __syncthreads();   // t0's g_fps writes visible CTA-wide
    for (int i=t;i<3*NQ;i+=512){
        int c=i>>10, s=i&1023;
        out1[b*3072 + i] = X[c*NPT + g_fps[b*NQ+s]];
    }
}

// ---------------- ball query: chunk-outer, float4, 4 queries/warp ---------
__global__ void __launch_bounds__(256) bq_kernel(const float* __restrict__ xyz,
                                                 const float* __restrict__ out1)
{
    __shared__ unsigned ebuf[8*128];
    int b = blockIdx.x >> 5, qb = blockIdx.x & 31;
    const float* Xx = xyz + b*3*NPT;
    const float* Xy = Xx + NPT;
    const float* Xz = Xx + 2*NPT;
    int wid = threadIdx.x>>5, lane = threadIdx.x&31;
    unsigned lt = (1u<<lane)-1u;
    unsigned* wbuf = ebuf + wid*128;
    int s0 = qb*32 + wid*4;
    float cx[4],cy[4],cz[4]; int cnt[4]={0,0,0,0}; unsigned gtag[4];
    #pragma unroll
    for (int q=0;q<4;q++){
        int s = s0+q;
        cx[q]=__ldg(out1 + b*3072 + s);
        cy[q]=__ldg(out1 + b*3072 + 1024 + s);
        cz[q]=__ldg(out1 + b*3072 + 2048 + s);
        gtag[q]=(unsigned)(b*NQ+s)<<12;
    }
    int wn = 0;
    for (int bp=0; bp<NPT; bp+=128){
        if (cnt[0]>=NSAMP && cnt[1]>=NSAMP && cnt[2]>=NSAMP && cnt[3]>=NSAMP) break;
        int p = bp + lane*4;
        float4 fx = __ldg((const float4*)(Xx+p));
        float4 fy = __ldg((const float4*)(Xy+p));
        float4 fz = __ldg((const float4*)(Xz+p));
        float pxl[4]={fx.x,fx.y,fx.z,fx.w};
        float pyl[4]={fy.x,fy.y,fy.z,fy.w};
        float pzl[4]={fz.x,fz.y,fz.z,fz.w};
        #pragma unroll
        for (int q=0;q<4;q++){
            if (cnt[q]>=NSAMP) continue;          // warp-uniform
            bool inb[4]; unsigned m[4];
            #pragma unroll
            for (int j=0;j<4;j++){
                float dx=pxl[j]-cx[q], dy=pyl[j]-cy[q], dz=pzl[j]-cz[q];
                float d2=__fadd_rn(__fadd_rn(__fmul_rn(dx,dx),__fmul_rn(dy,dy)),__fmul_rn(dz,dz));
                inb[j] = (d2 <= 0.04f);
                m[j] = __ballot_sync(FULLM, inb[j]);
            }
            int tot = __popc(m[0])+__popc(m[1])+__popc(m[2])+__popc(m[3]);
            if (!tot) continue;                    // warp-uniform
            if (cnt[q] + tot <= NSAMP){
                int off = wn;
                #pragma unroll
                for (int j=0;j<4;j++){
                    if (inb[j]) wbuf[off + __popc(m[j]&lt)] = gtag[q] | (unsigned)(p+j);
                    off += __popc(m[j]);
                }
                wn += tot; cnt[q] += tot;
            } else {
                // rare: crossing NSAMP — redo this 128-chunk in index order
                for (int sub=0; sub<4 && cnt[q]<NSAMP; ++sub){
                    int pp = bp + sub*32 + lane;
                    float dx=__ldg(Xx+pp)-cx[q], dy=__ldg(Xy+pp)-cy[q], dz=__ldg(Xz+pp)-cz[q];
                    float d2=__fadd_rn(__fadd_rn(__fmul_rn(dx,dx),__fmul_rn(dy,dy)),__fmul_rn(dz,dz));
                    bool in = (d2 <= 0.04f);
                    unsigned mask = __ballot_sync(FULLM, in);
                    int pc = __popc(mask);
                    int take = min(pc, NSAMP-cnt[q]);
                    if (in){
                        int pos = __popc(mask & lt);
                        if (pos < take) wbuf[wn+pos] = gtag[q] | (unsigned)pp;
                    }
                    wn += take; cnt[q] += take;
                }
            }
        }
    }
    int gb = 0;
    if (lane==0) gb = atomicAdd(&g_ecnt, wn);
    gb = __shfl_sync(FULLM, gb, 0);
    for (int i=lane;i<wn;i+=32) g_ent[gb+i] = wbuf[i];
}

// ---------------- fused 3-layer MLP on compacted entries + max scatter ---
__global__ void __launch_bounds__(256,3) mlp_kernel(const float* __restrict__ xyz,
                                                    const float* __restrict__ pts,
                                                    const float* __restrict__ out1,
                                                    float* __restrict__ out2)
{
    extern __shared__ float sm[];
    float* sX  = sm;            // 67*64 = 4288
    float* sH  = sm + 4288;     // 64*64 = 4096
    float* sB0 = sm + 8384;     // 64
    float* sB1 = sm + 8448;     // 64
    float* sB2 = sm + 8512;     // 128  (total 8640 floats = 34560 B)
    int t = threadIdx.x;
    if (t<64){ sB0[t]=g_B0[t]; sB1[t]=g_B1[t]; }
    if (t<128) sB2[t]=g_B2[t];
    int E = g_ecnt;
    int tiles = (E+63)>>6;
    int tx = t&15, ty = t>>4;
    int* outI = (int*)out2;
    int le = t>>2, sub = t&3;
    for (int tb = blockIdx.x; tb < tiles; tb += gridDim.x){
        int tbase = tb<<6;
        __syncthreads();
        {   // gather 67-channel input for 64 entries (4 threads / entry)
            int ge = tbase + le;
            unsigned raw = g_ent[ge < E ? ge : 0] & 0x3FFFFFFu;
            int p = raw & 4095; int g = raw >> 12; int bb = g >> 10, s = g & 1023;
            const float* pc = pts  + (size_t)(bb*64)*NPT + p;
            const float* xc = xyz  + (size_t)(bb*3)*NPT + p;
            const float* cc = out1 + bb*3*NQ + s;
            for (int c=sub;c<67;c+=4){
                float v;
                if (c<3) v = __ldg(xc + c*NPT) - __ldg(cc + c*NQ);
                else     v = __ldg(pc + (c-3)*NPT);
                sX[c*64+le] = v;
            }
        }
        __syncthreads();
        // ---- layer 0: 67 -> 64 ----
        float acc[4][4];
        #pragma unroll
        for (int j=0;j<4;j++){ float bb=sB0[ty*4+j];
            #pragma unroll
            for (int i=0;i<4;i++) acc[i][j]=bb; }
        #pragma unroll 4
        for (int k=0;k<67;k++){
            float4 xv = *(const float4*)&sX[k*64+tx*4];
            float4 wv = __ldg((const float4*)&g_W0[k*64+ty*4]);
            float xr[4]={xv.x,xv.y,xv.z,xv.w};
            float wr[4]={wv.x,wv.y,wv.z,wv.w};
            #pragma unroll
            for (int i=0;i<4;i++)
                #pragma unroll
                for (int j=0;j<4;j++) acc[i][j] = fmaf(xr[i],wr[j],acc[i][j]);
        }
        #pragma unroll
        for (int j=0;j<4;j++){
            float4 hv = make_float4(fmaxf(acc[0][j],0.f),fmaxf(acc[1][j],0.f),
                                    fmaxf(acc[2][j],0.f),fmaxf(acc[3][j],0.f));
            *(float4*)&sH[(ty*4+j)*64 + tx*4] = hv;
        }
        __syncthreads();
        // ---- layer 1: 64 -> 64 ----
        #pragma unroll
        for (int j=0;j<4;j++){ float bb=sB1[ty*4+j];
            #pragma unroll
            for (int i=0;i<4;i++) acc[i][j]=bb; }
        #pragma unroll 4
        for (int k=0;k<64;k++){
            float4 xv = *(const float4*)&sH[k*64+tx*4];
            float4 wv = __ldg((const float4*)&g_W1[k*64+ty*4]);
            float xr[4]={xv.x,xv.y,xv.z,xv.w};
            float wr[4]={wv.x,wv.y,wv.z,wv.w};
            #pragma unroll
            for (int i=0;i<4;i++)
                #pragma unroll
                for (int j=0;j<4;j++) acc[i][j] = fmaf(xr[i],wr[j],acc[i][j]);
        }
        #pragma unroll
        for (int j=0;j<4;j++){
            float4 hv = make_float4(fmaxf(acc[0][j],0.f),fmaxf(acc[1][j],0.f),
                                    fmaxf(acc[2][j],0.f),fmaxf(acc[3][j],0.f));
            *(float4*)&sX[(ty*4+j)*64 + tx*4] = hv;
        }
        __syncthreads();
        // ---- layer 2: 64 -> 128 + relu + merged atomicMax scatter ----
        float a2[4][8];
        #pragma unroll
        for (int j=0;j<8;j++){ float bb=sB2[ty*8+j];
            #pragma unroll
            for (int i=0;i<4;i++) a2[i][j]=bb; }
        #pragma unroll 2
        for (int k=0;k<64;k++){
            float4 xv = *(const float4*)&sX[k*64+tx*4];
            float4 wa = __ldg((const float4*)&g_W2[k*128+ty*8]);
            float4 wb = __ldg((const float4*)&g_W2[k*128+ty*8+4]);
            float xr[4]={xv.x,xv.y,xv.z,xv.w};
            float wr[8]={wa.x,wa.y,wa.z,wa.w,wb.x,wb.y,wb.z,wb.w};
            #pragma unroll
            for (int i=0;i<4;i++)
                #pragma unroll
                for (int j=0;j<8;j++) a2[i][j]=fmaf(xr[i],wr[j],a2[i][j]);
        }
        unsigned gid[4];
        #pragma unroll
        for (int i=0;i<4;i++){
            int ge = tbase + tx*4 + i;
            gid[i] = (ge < E) ? ((g_ent[ge] >> 12) & 0x3FFFu) : 0xFFFFFFFFu;
        }
        #pragma unroll
        for (int i=0;i<4;i++){
            if (gid[i]==0xFFFFFFFFu) continue;
            if (i>0 && gid[i]==gid[i-1]) continue;
            float mv[8];
            #pragma unroll
            for (int j=0;j<8;j++) mv[j]=a2[i][j];
            #pragma unroll
            for (int i2=1;i2<4;i2++){
                if (i+i2<4 && gid[i+i2]==gid[i]){
                    #pragma unroll
                    for (int j=0;j<8;j++) mv[j]=fmaxf(mv[j],a2[i+i2][j]);
                }
            }
            int bb = gid[i]>>10, s = gid[i]&1023;
            int* po = outI + (bb*128 + ty*8)*NQ + s;
            #pragma unroll
            for (int j=0;j<8;j++)
                atomicMax(po + j*NQ, __float_as_int(fmaxf(mv[j],0.f)));
        }
    }
}

extern "C" void kernel_launch(void* const* d_in, const int* in_sizes, int n_in,
                              void* d_out, int out_size)
{
    const float* xyz = (const float*)d_in[0];
    const float* pts = (const float*)d_in[1];
    float* out1 = (float*)d_out;
    float* out2 = out1 + OUT1SZ;

    prep_kernel<<<2048,256>>>(out2,
        (const float*)d_in[2],(const float*)d_in[3],(const float*)d_in[4],
        (const float*)d_in[5],(const float*)d_in[6],(const float*)d_in[7],
        (const float*)d_in[8],(const float*)d_in[9],(const float*)d_in[10],
        (const float*)d_in[11],(const float*)d_in[12],(const float*)d_in[13],
        (const float*)d_in[14],(const float*)d_in[15],(const float*)d_in[16],
        (const float*)d_in[17],(const float*)d_in[18],(const float*)d_in[19]);
    fps_kernel<<<16,512>>>(xyz, out1);
    bq_kernel<<<512,256>>>(xyz, out1);
    mlp_kernel<<<592,256,34560>>>(xyz, pts, out1, out2);
}